// round 9
// baseline (speedup 1.0000x reference)
#include <cuda_runtime.h>
#include <math.h>

// ROI max pooling, two-pass:
//   Pass 1: NCHW [2,256,38,38] -> NHWC scratch [2,38,38,256]; block (0,0,0)
//           also precomputes per-roi bin bounds into packed __device__ arrays.
//   Pass 2: grid = (roi, i). block = (64 c4-lanes, 7 j) = 448 threads.
//           Thread = one bin x 4 channels. Inner loop processes 2 rows x 4
//           predicated columns per iteration -> 8 independent LDG.128 in
//           flight before any consuming FMAX (MLP ~8 vs ~2 before).
//
// Bin math (non-negative ints == Python floor-div):
//   x1=floor(rx1/16),..., rh=y2-y1+1, rw=x2-x1+1
//   hstart_i = y1 + (i*rh)/7, hend_i = y1 + ((i+1)*rh+6)/7  (same for w/j)
// Coords in [0,607.9] => windows inside [0,38), non-empty; nh,nw <= 7.

#define N_IMG 2
#define CHN   256
#define C4    (CHN/4)            // 64
#define H_    38
#define W_    38
#define HW    (H_ * W_)
#define NUM_ROIS 256
#define OUT_H 7
#define OUT_W 7
#define BINS  (OUT_H * OUT_W)
#define SPATIAL_SCALE 0.0625f
#define PTHREADS (C4 * OUT_W)    // 448

__device__ float g_featT[N_IMG * HW * CHN];     // [N][H][W][C]
__device__ int   g_base4[NUM_ROIS];             // b * HW * C4 (float4 units)
__device__ int   g_hb[NUM_ROIS * OUT_H];        // hstart | hend<<8
__device__ int   g_wb[NUM_ROIS * OUT_W];        // wstart | wend<<8

// ---------------------------------------------------------------------------
__global__ void transpose_kernel(const float* __restrict__ in,
                                 const float* __restrict__ rois)
{
    __shared__ float tile[32][33];
    int n   = blockIdx.z;
    int hw0 = blockIdx.x * 32;
    int c0  = blockIdx.y * 32;

    if (blockIdx.x == 0 && blockIdx.y == 0 && blockIdx.z == 0) {
        int t = threadIdx.y * 32 + threadIdx.x;     // 0..255
        if (t < NUM_ROIS) {
            const float* r = rois + t * 5;
            int b  = (int)r[0];
            int x1 = (int)floorf(r[1] * SPATIAL_SCALE);
            int y1 = (int)floorf(r[2] * SPATIAL_SCALE);
            int x2 = (int)floorf(r[3] * SPATIAL_SCALE);
            int y2 = (int)floorf(r[4] * SPATIAL_SCALE);
            int rh = y2 - y1 + 1;
            int rw = x2 - x1 + 1;
            g_base4[t] = b * HW * C4;
            #pragma unroll
            for (int i = 0; i < OUT_H; ++i) {
                int hs = y1 + (i * rh) / OUT_H;
                int he = y1 + ((i + 1) * rh + OUT_H - 1) / OUT_H;
                g_hb[t * OUT_H + i] = hs | (he << 8);
            }
            #pragma unroll
            for (int j = 0; j < OUT_W; ++j) {
                int ws = x1 + (j * rw) / OUT_W;
                int we = x1 + ((j + 1) * rw + OUT_W - 1) / OUT_W;
                g_wb[t * OUT_W + j] = ws | (we << 8);
            }
        }
    }

    const float* inp  = in      + (size_t)n * CHN * HW;
    float*       outp = g_featT + (size_t)n * HW * CHN;

    #pragma unroll
    for (int k = 0; k < 32; k += 8) {
        int c  = c0 + threadIdx.y + k;
        int hw = hw0 + threadIdx.x;
        tile[threadIdx.y + k][threadIdx.x] =
            (hw < HW) ? inp[(size_t)c * HW + hw] : 0.0f;
    }
    __syncthreads();
    #pragma unroll
    for (int k = 0; k < 32; k += 8) {
        int hw = hw0 + threadIdx.y + k;
        if (hw < HW)
            outp[(size_t)hw * CHN + c0 + threadIdx.x] =
                tile[threadIdx.x][threadIdx.y + k];
    }
}

__device__ __forceinline__ float4 max4(float4 a, float4 b)
{
    return make_float4(fmaxf(a.x, b.x), fmaxf(a.y, b.y),
                       fmaxf(a.z, b.z), fmaxf(a.w, b.w));
}

// ---------------------------------------------------------------------------
// Pass 2: grid = (NUM_ROIS, OUT_H), block = (C4, OUT_W) = (64, 7)
// ---------------------------------------------------------------------------
__global__ void __launch_bounds__(PTHREADS, 3)
roi_pool_bin(float* __restrict__ out)
{
    __shared__ float s[CHN * OUT_W];      // s[c*7 + j]

    int roi  = blockIdx.x;
    int i    = blockIdx.y;
    int lane = threadIdx.x;               // c4 index
    int j    = threadIdx.y;               // warp-uniform

    int hb = g_hb[roi * OUT_H + i];
    int wb = g_wb[roi * OUT_W + j];
    int hstart = hb & 0xff, hend = hb >> 8;
    int wstart = wb & 0xff, wend = wb >> 8;
    int nw = wend - wstart;               // 1..7, warp-uniform

    const float4* base = (const float4*)g_featT + g_base4[roi] + lane;
    const float NI = -__int_as_float(0x7f800000);
    const float4 NI4 = make_float4(NI, NI, NI, NI);

    float4 m[4];
    #pragma unroll
    for (int k = 0; k < 4; ++k) m[k] = NI4;

    // 2 rows x 4 predicated cols per iteration: 8 independent loads in flight.
    for (int h = hstart; h < hend; h += 2) {
        const float4* p0 = base + (size_t)(h * W_ + wstart) * C4;
        const float4* p1 = p0 + W_ * C4;
        bool r2 = (h + 1 < hend);

        float4 a0 = (0 < nw)       ? p0[0 * C4] : NI4;
        float4 a1 = (1 < nw)       ? p0[1 * C4] : NI4;
        float4 a2 = (2 < nw)       ? p0[2 * C4] : NI4;
        float4 a3 = (3 < nw)       ? p0[3 * C4] : NI4;
        float4 b0 = (r2 && 0 < nw) ? p1[0 * C4] : NI4;
        float4 b1 = (r2 && 1 < nw) ? p1[1 * C4] : NI4;
        float4 b2 = (r2 && 2 < nw) ? p1[2 * C4] : NI4;
        float4 b3 = (r2 && 3 < nw) ? p1[3 * C4] : NI4;

        m[0] = max4(m[0], max4(a0, b0));
        m[1] = max4(m[1], max4(a1, b1));
        m[2] = max4(m[2], max4(a2, b2));
        m[3] = max4(m[3], max4(a3, b3));

        // residual columns 4..nw-1 (<=3 iterations, warp-uniform)
        for (int k = 4; k < nw; ++k) {
            float4 a = p0[k * C4];
            float4 b = r2 ? p1[k * C4] : a;
            m[k - 4] = max4(m[k - 4], max4(a, b));
        }
    }
    float4 mm = max4(max4(m[0], m[1]), max4(m[2], m[3]));

    // stage as s[c*7 + j]
    int c0 = lane * 4;
    s[(c0 + 0) * OUT_W + j] = mm.x;
    s[(c0 + 1) * OUT_W + j] = mm.y;
    s[(c0 + 2) * OUT_W + j] = mm.z;
    s[(c0 + 3) * OUT_W + j] = mm.w;
    __syncthreads();

    // out[roi][c][i*7 + jj]; linear smem read, one div-by-7 per thread
    int tid = threadIdx.y * C4 + threadIdx.x;     // 0..447
    int cq  = tid / OUT_W;
    int jr  = tid - cq * OUT_W;
    float* ob = out + (size_t)roi * CHN * BINS + i * OUT_W + jr;
    #pragma unroll
    for (int k = 0; k < 4; ++k)
        ob[(size_t)(cq + 64 * k) * BINS] = s[tid + k * PTHREADS];
}

extern "C" void kernel_launch(void* const* d_in, const int* in_sizes, int n_in,
                              void* d_out, int out_size)
{
    const float* feat = (const float*)d_in[0];
    const float* rois = (const float*)d_in[1];
    float* out = (float*)d_out;

    dim3 tgrid((HW + 31) / 32, CHN / 32, N_IMG);
    dim3 tblock(32, 8);
    transpose_kernel<<<tgrid, tblock>>>(feat, rois);

    dim3 pgrid(NUM_ROIS, OUT_H);
    dim3 pblock(C4, OUT_W);
    roi_pool_bin<<<pgrid, pblock>>>(out);
}

// round 10
// speedup vs baseline: 1.6544x; 1.6544x over previous
#include <cuda_runtime.h>
#include <math.h>

// ROI max pooling, two-pass:
//   Pass 1: NCHW [2,256,38,38] -> NHWC scratch [2,38,38,256]; block (0,0,0)
//           also precomputes per-roi bin bounds into packed __device__ arrays.
//   Pass 2: grid = (roi, i). block = (32 lanes, 7 j) = 224 threads.
//           Thread = one bin x 8 channels (c4 lanes `lane` and `lane+32`).
//           Inner loop: w-unroll-by-2 => 4 unconditional independent
//           LDG.128 per iteration into 4 independent accumulators.
//
// Bin math (non-negative ints == Python floor-div):
//   x1=floor(rx1/16),..., rh=y2-y1+1, rw=x2-x1+1
//   hstart_i = y1 + (i*rh)/7, hend_i = y1 + ((i+1)*rh+6)/7  (same for w/j)
// Coords in [0,607.9] => windows inside [0,38), non-empty.

#define N_IMG 2
#define CHN   256
#define C4    (CHN/4)            // 64
#define H_    38
#define W_    38
#define HW    (H_ * W_)
#define NUM_ROIS 256
#define OUT_H 7
#define OUT_W 7
#define BINS  (OUT_H * OUT_W)
#define SPATIAL_SCALE 0.0625f
#define LANES 32
#define PTHREADS (LANES * OUT_W)  // 224

__device__ float g_featT[N_IMG * HW * CHN];     // [N][H][W][C]
__device__ int   g_base4[NUM_ROIS];             // b * HW * C4 (float4 units)
__device__ int   g_hb[NUM_ROIS * OUT_H];        // hstart | hend<<8
__device__ int   g_wb[NUM_ROIS * OUT_W];        // wstart | wend<<8

// ---------------------------------------------------------------------------
__global__ void transpose_kernel(const float* __restrict__ in,
                                 const float* __restrict__ rois)
{
    __shared__ float tile[32][33];
    int n   = blockIdx.z;
    int hw0 = blockIdx.x * 32;
    int c0  = blockIdx.y * 32;

    if (blockIdx.x == 0 && blockIdx.y == 0 && blockIdx.z == 0) {
        int t = threadIdx.y * 32 + threadIdx.x;     // 0..255
        if (t < NUM_ROIS) {
            const float* r = rois + t * 5;
            int b  = (int)r[0];
            int x1 = (int)floorf(r[1] * SPATIAL_SCALE);
            int y1 = (int)floorf(r[2] * SPATIAL_SCALE);
            int x2 = (int)floorf(r[3] * SPATIAL_SCALE);
            int y2 = (int)floorf(r[4] * SPATIAL_SCALE);
            int rh = y2 - y1 + 1;
            int rw = x2 - x1 + 1;
            g_base4[t] = b * HW * C4;
            #pragma unroll
            for (int i = 0; i < OUT_H; ++i) {
                int hs = y1 + (i * rh) / OUT_H;
                int he = y1 + ((i + 1) * rh + OUT_H - 1) / OUT_H;
                g_hb[t * OUT_H + i] = hs | (he << 8);
            }
            #pragma unroll
            for (int j = 0; j < OUT_W; ++j) {
                int ws = x1 + (j * rw) / OUT_W;
                int we = x1 + ((j + 1) * rw + OUT_W - 1) / OUT_W;
                g_wb[t * OUT_W + j] = ws | (we << 8);
            }
        }
    }

    const float* inp  = in      + (size_t)n * CHN * HW;
    float*       outp = g_featT + (size_t)n * HW * CHN;

    #pragma unroll
    for (int k = 0; k < 32; k += 8) {
        int c  = c0 + threadIdx.y + k;
        int hw = hw0 + threadIdx.x;
        tile[threadIdx.y + k][threadIdx.x] =
            (hw < HW) ? inp[(size_t)c * HW + hw] : 0.0f;
    }
    __syncthreads();
    #pragma unroll
    for (int k = 0; k < 32; k += 8) {
        int hw = hw0 + threadIdx.y + k;
        if (hw < HW)
            outp[(size_t)hw * CHN + c0 + threadIdx.x] =
                tile[threadIdx.x][threadIdx.y + k];
    }
}

__device__ __forceinline__ float4 max4(float4 a, float4 b)
{
    return make_float4(fmaxf(a.x, b.x), fmaxf(a.y, b.y),
                       fmaxf(a.z, b.z), fmaxf(a.w, b.w));
}

// ---------------------------------------------------------------------------
// Pass 2: grid = (NUM_ROIS, OUT_H), block = (LANES, OUT_W) = (32, 7)
// ---------------------------------------------------------------------------
__global__ void __launch_bounds__(PTHREADS, 7)
roi_pool_bin(float* __restrict__ out)
{
    __shared__ float s[CHN * OUT_W];      // s[c*7 + j]

    int roi  = blockIdx.x;
    int i    = blockIdx.y;
    int lane = threadIdx.x;               // c4 lanes: lane and lane+32
    int j    = threadIdx.y;               // warp-uniform

    int hb = g_hb[roi * OUT_H + i];
    int wb = g_wb[roi * OUT_W + j];
    int hstart = hb & 0xff, hend = hb >> 8;
    int wstart = wb & 0xff, wend = wb >> 8;
    int nw = wend - wstart;               // 1..7, warp-uniform

    const float4* base = (const float4*)g_featT + g_base4[roi] + lane;
    const float NI = -__int_as_float(0x7f800000);
    float4 m0 = make_float4(NI, NI, NI, NI);
    float4 m1 = m0, m2 = m0, m3 = m0;

    for (int h = hstart; h < hend; ++h) {
        const float4* p = base + (size_t)(h * W_ + wstart) * C4;
        int w = nw;
        while (w >= 2) {
            m0 = max4(m0, p[0]);
            m1 = max4(m1, p[LANES]);
            m2 = max4(m2, p[C4]);
            m3 = max4(m3, p[C4 + LANES]);
            p += 2 * C4;
            w -= 2;
        }
        if (w) {
            m0 = max4(m0, p[0]);
            m1 = max4(m1, p[LANES]);
        }
    }
    float4 mA = max4(m0, m2);     // channels lane*4 .. lane*4+3
    float4 mB = max4(m1, m3);     // channels (lane+32)*4 ..

    int c0 = lane * 4;
    s[(c0 + 0) * OUT_W + j] = mA.x;
    s[(c0 + 1) * OUT_W + j] = mA.y;
    s[(c0 + 2) * OUT_W + j] = mA.z;
    s[(c0 + 3) * OUT_W + j] = mA.w;
    s[(c0 + 128) * OUT_W + j] = mB.x;
    s[(c0 + 129) * OUT_W + j] = mB.y;
    s[(c0 + 130) * OUT_W + j] = mB.z;
    s[(c0 + 131) * OUT_W + j] = mB.w;
    __syncthreads();

    // out[roi][c][i*7 + jj]; linear smem read, one div-by-7 per thread
    int tid = threadIdx.y * LANES + threadIdx.x;   // 0..223
    int cq  = tid / OUT_W;
    int jr  = tid - cq * OUT_W;
    float* ob = out + (size_t)roi * CHN * BINS + i * OUT_W + jr;
    #pragma unroll
    for (int k = 0; k < 8; ++k)
        ob[(size_t)(cq + 32 * k) * BINS] = s[tid + k * PTHREADS];
}

extern "C" void kernel_launch(void* const* d_in, const int* in_sizes, int n_in,
                              void* d_out, int out_size)
{
    const float* feat = (const float*)d_in[0];
    const float* rois = (const float*)d_in[1];
    float* out = (float*)d_out;

    dim3 tgrid((HW + 31) / 32, CHN / 32, N_IMG);
    dim3 tblock(32, 8);
    transpose_kernel<<<tgrid, tblock>>>(feat, rois);

    dim3 pgrid(NUM_ROIS, OUT_H);
    dim3 pblock(LANES, OUT_W);
    roi_pool_bin<<<pgrid, pblock>>>(out);
}

// round 12
// speedup vs baseline: 1.7336x; 1.0479x over previous
#include <cuda_runtime.h>
#include <math.h>

// ROI max pooling, two-pass:
//   Pass 1: NCHW [2,256,38,38] -> NHWC scratch [2,38,38,256]; block (0,0,0)
//           also precomputes per-roi bin bounds into packed __device__ arrays.
//   Pass 2: grid = (roi, i). block = (64 c4-lanes, 7 j) = 448 threads.
//           Thread = one bin x 4 channels. nw is warp-uniform (1..7);
//           switch-dispatch to a template<NW> body => per row, NW
//           unconditional back-to-back LDG.128 into rotating accumulators.
//
// Bin math (non-negative ints == Python floor-div):
//   x1=floor(rx1/16),..., rh=y2-y1+1, rw=x2-x1+1
//   hstart_i = y1 + (i*rh)/7, hend_i = y1 + ((i+1)*rh+6)/7  (same for w/j)
// Coords in [0,607.9] => windows inside [0,38), non-empty; nh,nw in [1,7].

#define N_IMG 2
#define CHN   256
#define C4    (CHN/4)            // 64
#define H_    38
#define W_    38
#define HW    (H_ * W_)
#define NUM_ROIS 256
#define OUT_H 7
#define OUT_W 7
#define BINS  (OUT_H * OUT_W)
#define SPATIAL_SCALE 0.0625f
#define PTHREADS (C4 * OUT_W)    // 448

__device__ float g_featT[N_IMG * HW * CHN];     // [N][H][W][C]
__device__ int   g_base4[NUM_ROIS];             // b * HW * C4 (float4 units)
__device__ int   g_hb[NUM_ROIS * OUT_H];        // hstart | hend<<8
__device__ int   g_wb[NUM_ROIS * OUT_W];        // wstart | wend<<8

// ---------------------------------------------------------------------------
__global__ void transpose_kernel(const float* __restrict__ in,
                                 const float* __restrict__ rois)
{
    __shared__ float tile[32][33];
    int n   = blockIdx.z;
    int hw0 = blockIdx.x * 32;
    int c0  = blockIdx.y * 32;

    if (blockIdx.x == 0 && blockIdx.y == 0 && blockIdx.z == 0) {
        int t = threadIdx.y * 32 + threadIdx.x;     // 0..255
        if (t < NUM_ROIS) {
            const float* r = rois + t * 5;
            int b  = (int)r[0];
            int x1 = (int)floorf(r[1] * SPATIAL_SCALE);
            int y1 = (int)floorf(r[2] * SPATIAL_SCALE);
            int x2 = (int)floorf(r[3] * SPATIAL_SCALE);
            int y2 = (int)floorf(r[4] * SPATIAL_SCALE);
            int rh = y2 - y1 + 1;
            int rw = x2 - x1 + 1;
            g_base4[t] = b * HW * C4;
            #pragma unroll
            for (int i = 0; i < OUT_H; ++i) {
                int hs = y1 + (i * rh) / OUT_H;
                int he = y1 + ((i + 1) * rh + OUT_H - 1) / OUT_H;
                g_hb[t * OUT_H + i] = hs | (he << 8);
            }
            #pragma unroll
            for (int j = 0; j < OUT_W; ++j) {
                int ws = x1 + (j * rw) / OUT_W;
                int we = x1 + ((j + 1) * rw + OUT_W - 1) / OUT_W;
                g_wb[t * OUT_W + j] = ws | (we << 8);
            }
        }
    }

    const float* inp  = in      + (size_t)n * CHN * HW;
    float*       outp = g_featT + (size_t)n * HW * CHN;

    #pragma unroll
    for (int k = 0; k < 32; k += 8) {
        int c  = c0 + threadIdx.y + k;
        int hw = hw0 + threadIdx.x;
        tile[threadIdx.y + k][threadIdx.x] =
            (hw < HW) ? inp[(size_t)c * HW + hw] : 0.0f;
    }
    __syncthreads();
    #pragma unroll
    for (int k = 0; k < 32; k += 8) {
        int hw = hw0 + threadIdx.y + k;
        if (hw < HW)
            outp[(size_t)hw * CHN + c0 + threadIdx.x] =
                tile[threadIdx.x][threadIdx.y + k];
    }
}

__device__ __forceinline__ float4 max4(float4 a, float4 b)
{
    return make_float4(fmaxf(a.x, b.x), fmaxf(a.y, b.y),
                       fmaxf(a.z, b.z), fmaxf(a.w, b.w));
}

// Compile-time-NW pooling body: per row, NW unconditional independent loads.
template<int NW>
__device__ __forceinline__ float4 pool_nw(const float4* __restrict__ base,
                                          int hstart, int hend, int wstart)
{
    const float NI = -__int_as_float(0x7f800000);
    float4 m[4];
    #pragma unroll
    for (int k = 0; k < 4; ++k) m[k] = make_float4(NI, NI, NI, NI);

    const float4* p = base + (size_t)(hstart * W_ + wstart) * C4;
    #pragma unroll 2
    for (int h = hstart; h < hend; ++h) {
        #pragma unroll
        for (int w = 0; w < NW; ++w)
            m[w & 3] = max4(m[w & 3], p[w * C4]);
        p += W_ * C4;
    }
    return max4(max4(m[0], m[1]), max4(m[2], m[3]));
}

// ---------------------------------------------------------------------------
// Pass 2: grid = (NUM_ROIS, OUT_H), block = (C4, OUT_W) = (64, 7)
// ---------------------------------------------------------------------------
__global__ void __launch_bounds__(PTHREADS, 3)
roi_pool_bin(float* __restrict__ out)
{
    __shared__ float s[CHN * OUT_W];      // s[c*7 + j]

    int roi  = blockIdx.x;
    int i    = blockIdx.y;
    int lane = threadIdx.x;               // c4 index
    int j    = threadIdx.y;               // warp-uniform

    int hb = g_hb[roi * OUT_H + i];
    int wb = g_wb[roi * OUT_W + j];
    int hstart = hb & 0xff, hend = hb >> 8;
    int wstart = wb & 0xff, wend = wb >> 8;
    int nw = wend - wstart;               // 1..7, warp-uniform

    const float4* base = (const float4*)g_featT + g_base4[roi] + lane;

    float4 m;
    switch (nw) {
        case 1: m = pool_nw<1>(base, hstart, hend, wstart); break;
        case 2: m = pool_nw<2>(base, hstart, hend, wstart); break;
        case 3: m = pool_nw<3>(base, hstart, hend, wstart); break;
        case 4: m = pool_nw<4>(base, hstart, hend, wstart); break;
        case 5: m = pool_nw<5>(base, hstart, hend, wstart); break;
        case 6: m = pool_nw<6>(base, hstart, hend, wstart); break;
        default: m = pool_nw<7>(base, hstart, hend, wstart); break;
    }

    // stage as s[c*7 + j]
    int c0 = lane * 4;
    s[(c0 + 0) * OUT_W + j] = m.x;
    s[(c0 + 1) * OUT_W + j] = m.y;
    s[(c0 + 2) * OUT_W + j] = m.z;
    s[(c0 + 3) * OUT_W + j] = m.w;
    __syncthreads();

    // out[roi][c][i*7 + jj]; linear smem read, one div-by-7 per thread
    int tid = threadIdx.y * C4 + threadIdx.x;     // 0..447
    int cq  = tid / OUT_W;
    int jr  = tid - cq * OUT_W;
    float* ob = out + (size_t)roi * CHN * BINS + i * OUT_W + jr;
    #pragma unroll
    for (int k = 0; k < 4; ++k)
        ob[(size_t)(cq + 64 * k) * BINS] = s[tid + k * PTHREADS];
}

extern "C" void kernel_launch(void* const* d_in, const int* in_sizes, int n_in,
                              void* d_out, int out_size)
{
    const float* feat = (const float*)d_in[0];
    const float* rois = (const float*)d_in[1];
    float* out = (float*)d_out;

    dim3 tgrid((HW + 31) / 32, CHN / 32, N_IMG);
    dim3 tblock(32, 8);
    transpose_kernel<<<tgrid, tblock>>>(feat, rois);

    dim3 pgrid(NUM_ROIS, OUT_H);
    dim3 pblock(C4, OUT_W);
    roi_pool_bin<<<pgrid, pblock>>>(out);
}